// round 11
// baseline (speedup 1.0000x reference)
#include <cuda_runtime.h>
#include <cuda_bf16.h>
#include <cstdint>

#define NC   81
#define NCP  96
#define BK   10
#define DIM  2048
#define NI   16384
#define NT   64
#define BMG  128

__device__ int   g_count;
__device__ int   g_nfix;
__device__ int   g_tick;
__device__ int   g_fix[NI];
__device__ float g_bias[NCP];
__device__ float g_mmean[NC * DIM];
__device__ __align__(16) unsigned short g_mbf[NT * NCP * 64];

__device__ __forceinline__ uint32_t smem_u32(const void* p) {
    uint32_t a;
    asm("{ .reg .u64 t; cvta.to.shared.u64 t, %1; cvt.u32.u64 %0, t; }" : "=r"(a) : "l"(p));
    return a;
}

#define LDSM_X4(r0, r1, r2, r3, addr)                                         \
    asm volatile("ldmatrix.sync.aligned.m8n8.x4.shared.b16 {%0,%1,%2,%3}, [%4];" \
                 : "=r"(r0), "=r"(r1), "=r"(r2), "=r"(r3) : "r"(addr))

#define MMA16816(d, a, b0v, b1v)                                              \
    asm volatile("mma.sync.aligned.m16n8k16.row.col.f32.bf16.bf16.f32 "       \
                 "{%0,%1,%2,%3},{%4,%5,%6,%7},{%8,%9},{%0,%1,%2,%3};"         \
                 : "+f"((d)[0]), "+f"((d)[1]), "+f"((d)[2]), "+f"((d)[3])     \
                 : "r"((a)[0]), "r"((a)[1]), "r"((a)[2]), "r"((a)[3]),        \
                   "r"(b0v), "r"(b1v))

#define FMA2(d, a, b, c) asm("fma.rn.f32x2 %0, %1, %2, %3;" : "=l"(d) : "l"(a), "l"(b), "l"(c))
#define UNPACK2(lo, hi, v) asm("mov.b64 {%0, %1}, %2;" : "=f"(lo), "=f"(hi) : "l"(v))

#define CPA16(dst, src) asm volatile("cp.async.cg.shared.global [%0], [%1], 16;" :: "r"(dst), "l"(src) : "memory")
#define CPCOMMIT()      asm volatile("cp.async.commit_group;" ::: "memory")
#define CPWAIT0()       asm volatile("cp.async.wait_group 0;" ::: "memory")

__device__ __forceinline__ unsigned pkbf(__nv_bfloat16 a, __nv_bfloat16 b) {
    return ((unsigned)__bfloat16_as_ushort(b) << 16) | (unsigned)__bfloat16_as_ushort(a);
}

__device__ __forceinline__ float pdot(ulonglong2 A0, ulonglong2 A1,
                                      ulonglong2 B0, ulonglong2 B1) {
    unsigned long long pa = 0ull;
    FMA2(pa, A0.x, B0.x, pa); FMA2(pa, A0.y, B0.y, pa);
    FMA2(pa, A1.x, B1.x, pa); FMA2(pa, A1.y, B1.y, pa);
    float lo, hi; UNPACK2(lo, hi, pa);
    return lo + hi;
}

// ---------------------------------------------------------------------------
// Kernel 1: class means -> fp32 plane + bf16 hi/lo planes + bias; zero pads.
// ---------------------------------------------------------------------------
__global__ void k_mean(const float* __restrict__ mem) {
    int c = blockIdx.x, tid = threadIdx.x;
    if (c == 0 && tid == 0) { g_count = 0; g_nfix = 0; g_tick = 0; }
    if (c >= NC) {
        for (int d = tid; d < DIM; d += 256) {
            int tt = d >> 5, j = d & 31;
            g_mbf[(tt * NCP + c) * 64 + j] = 0;
            g_mbf[(tt * NCP + c) * 64 + 32 + j] = 0;
        }
        return;
    }
    float part = 0.f;
    for (int d = tid; d < DIM; d += 256) {
        float s = 0.f;
#pragma unroll
        for (int b = 0; b < BK; b++) s += mem[(size_t)(c * BK + b) * DIM + d];
        float m = s * (1.0f / BK);
        g_mmean[c * DIM + d] = m;
        __nv_bfloat16 hi = __float2bfloat16_rn(m);
        __nv_bfloat16 lo = __float2bfloat16_rn(m - __bfloat162float(hi));
        int tt = d >> 5, j = d & 31;
        g_mbf[(tt * NCP + c) * 64 + j] = __bfloat16_as_ushort(hi);
        g_mbf[(tt * NCP + c) * 64 + 32 + j] = __bfloat16_as_ushort(lo);
        part += m * m;
    }
#pragma unroll
    for (int o = 16; o; o >>= 1) part += __shfl_xor_sync(0xffffffffu, part, o);
    __shared__ float rb[8];
    if ((tid & 31) == 0) rb[tid >> 5] = part;
    __syncthreads();
    if (tid == 0) {
        float t = 0.f;
#pragma unroll
        for (int w = 0; w < 8; w++) t += rb[w];
        g_bias[c] = 0.5f * t;
    }
}

// ---------------------------------------------------------------------------
// GEMM path (blocks >= 81): HMMA bf16-split GEMM + argmin + fixup list.
// ---------------------------------------------------------------------------
#define STAGE 28672
#define SMEM_FUSED 197632

__device__ __forceinline__ void gemm_path(char* sm, const float* __restrict__ X,
                                          const int* __restrict__ labels,
                                          float* __restrict__ out, int gb) {
    const uint32_t sb = smem_u32(sm);
    const int tid = threadIdx.x, wid = tid >> 5, lane = tid & 31;
    const int i0 = gb * BMG;
    const int mwarp = wid & 3, nwarp = wid >> 2;

    const int r = tid >> 1, h = tid & 1;
    const float* xrow = X + (size_t)(i0 + r) * DIM + h * 16;
    const uint4* mb4 = (const uint4*)g_mbf;

    float d[2][6][4];
#pragma unroll
    for (int a = 0; a < 2; a++)
#pragma unroll
        for (int b = 0; b < 6; b++)
#pragma unroll
            for (int e = 0; e < 4; e++) d[a][b][e] = 0.f;

    float4 cur0, cur1, cur2, cur3;
#define GLOAD(t)                                                    \
    {   const float4* p4 = (const float4*)(xrow + (t) * 32);        \
        cur0 = p4[0]; cur1 = p4[1]; cur2 = p4[2]; cur3 = p4[3]; }

#define GSTORE(t, buf)                                                          \
    {   float f[16];                                                            \
        *(float4*)(f + 0) = cur0; *(float4*)(f + 4) = cur1;                     \
        *(float4*)(f + 8) = cur2; *(float4*)(f + 12) = cur3;                    \
        unsigned hw[8], lw[8];                                                  \
        _Pragma("unroll") for (int j = 0; j < 8; j++) {                         \
            float x0 = f[2 * j], x1 = f[2 * j + 1];                             \
            __nv_bfloat16 h0 = __float2bfloat16_rn(x0);                         \
            __nv_bfloat16 h1 = __float2bfloat16_rn(x1);                         \
            __nv_bfloat16 l0 = __float2bfloat16_rn(x0 - __bfloat162float(h0));  \
            __nv_bfloat16 l1 = __float2bfloat16_rn(x1 - __bfloat162float(h1));  \
            hw[j] = pkbf(h0, h1); lw[j] = pkbf(l0, l1);                         \
        }                                                                       \
        char* Ab = sm + (buf) * STAGE;                                          \
        const int rx = r & 7;                                                   \
        *(uint4*)(Ab + r * 128 + 16 * ((2 * h + 0) ^ rx)) = make_uint4(hw[0], hw[1], hw[2], hw[3]); \
        *(uint4*)(Ab + r * 128 + 16 * ((2 * h + 1) ^ rx)) = make_uint4(hw[4], hw[5], hw[6], hw[7]); \
        *(uint4*)(Ab + r * 128 + 16 * ((4 + 2 * h) ^ rx)) = make_uint4(lw[0], lw[1], lw[2], lw[3]); \
        *(uint4*)(Ab + r * 128 + 16 * ((5 + 2 * h) ^ rx)) = make_uint4(lw[4], lw[5], lw[6], lw[7]); \
        char* Bb = Ab + 16384;                                                  \
        _Pragma("unroll") for (int q = 0; q < 3; q++) {                         \
            int g = tid + q * 256;                                              \
            int brow = g >> 3, bch = g & 7;                                     \
            *(uint4*)(Bb + brow * 128 + 16 * (bch ^ (brow & 7))) = mb4[(t) * 768 + g]; \
        }                                                                       \
    }

    GLOAD(0);
    GSTORE(0, 0);

    for (int t = 0; t < NT; t++) {
        const int buf = t & 1;
        if (t + 1 < NT) GLOAD(t + 1);
        __syncthreads();

        const uint32_t Abase = sb + buf * STAGE;
        const uint32_t Bbase = Abase + 16384;

        uint32_t afr[2][2][2][4];
#pragma unroll
        for (int mt = 0; mt < 2; mt++) {
            int rowA = mwarp * 32 + mt * 16 + (lane & 15);
            uint32_t rbase = Abase + rowA * 128;
            int rx = rowA & 7;
#pragma unroll
            for (int pl = 0; pl < 2; pl++)
#pragma unroll
                for (int s = 0; s < 2; s++) {
                    int ch = pl * 4 + s * 2 + (lane >> 4);
                    uint32_t ad = rbase + 16 * (ch ^ rx);
                    LDSM_X4(afr[mt][pl][s][0], afr[mt][pl][s][1],
                            afr[mt][pl][s][2], afr[mt][pl][s][3], ad);
                }
        }

#pragma unroll
        for (int pp = 0; pp < 3; pp++) {
            const int apl = (pp == 2) ? 1 : 0;
            const int bpl = (pp == 1) ? 1 : 0;
#pragma unroll
            for (int np = 0; np < 3; np++) {
                int rowB = nwarp * 48 + np * 16 + (lane & 15);
                uint32_t rbase = Bbase + rowB * 128;
                int rx = rowB & 7;
#pragma unroll
                for (int s = 0; s < 2; s++) {
                    int ch = bpl * 4 + s * 2 + (lane >> 4);
                    uint32_t bd = rbase + 16 * (ch ^ rx);
                    uint32_t b0, b1, b2, b3;
                    LDSM_X4(b0, b1, b2, b3, bd);
#pragma unroll
                    for (int mt = 0; mt < 2; mt++) {
                        MMA16816(d[mt][np * 2 + 0], afr[mt][apl][s], b0, b2);
                        MMA16816(d[mt][np * 2 + 1], afr[mt][apl][s], b1, b3);
                    }
                }
            }
        }
        __syncthreads();
        if (t + 1 < NT) GSTORE(t + 1, (t + 1) & 1);
    }
    __syncthreads();

    float* sc = (float*)sm;
#pragma unroll
    for (int mt = 0; mt < 2; mt++) {
#pragma unroll
        for (int np = 0; np < 3; np++)
#pragma unroll
            for (int hh = 0; hh < 2; hh++) {
                int row0 = mwarp * 32 + mt * 16 + (lane >> 2);
                int col0 = nwarp * 48 + np * 16 + hh * 8 + 2 * (lane & 3);
                const float* dd = d[mt][np * 2 + hh];
                if (col0 < NC) sc[row0 * 97 + col0] = g_bias[col0] - dd[0];
                if (col0 + 1 < NC) sc[row0 * 97 + col0 + 1] = g_bias[col0 + 1] - dd[1];
                if (col0 < NC) sc[(row0 + 8) * 97 + col0] = g_bias[col0] - dd[2];
                if (col0 + 1 < NC) sc[(row0 + 8) * 97 + col0 + 1] = g_bias[col0 + 1] - dd[3];
            }
    }
    __syncthreads();

    if (tid < BMG) {
        int gi = i0 + tid;
        const float* row = sc + tid * 97;
        float best = 3e38f, sec = 3e38f;
        int bc = 0;
#pragma unroll 4
        for (int cc = 0; cc < NC; cc++) {
            float v = row[cc];
            if (v < best) { sec = best; best = v; bc = cc; }
            else if (v < sec) sec = v;
        }
        out[gi] = (float)bc;
        if (sec - best < 0.02f) {
            int slot = atomicAdd(&g_nfix, 1);
            if (slot < NI) g_fix[slot] = gi;
        }
        unsigned bal = __ballot_sync(0xffffffffu, bc == labels[gi]);
        if ((tid & 31) == 0) atomicAdd(&g_count, __popc(bal));
    }
}

// ---------------------------------------------------------------------------
// Update path (blocks 0..80): CHUNKED sequential update, T=8.
// Per chunk: 116 parallel dot rows (80 D vs bank-at-chunk-start, 28 intra-
// chunk pairs P[i<t], 8 norms) -> two reduce phases -> scalar 8-step
// recurrence on broadcast values (exact; P patches replaced slots) -> apply.
// smem: ring 2x8x8192=128K @0 | s_part 60x1K @131072 | s_red 128f @192512 |
//       s_list 4K @193024 | s_wcnt @197120 | s_cnt @197152
// ---------------------------------------------------------------------------
__device__ __forceinline__ void update_path(char* smu, const float* __restrict__ X,
                                            const int* __restrict__ labels,
                                            const float* __restrict__ mem,
                                            const int* __restrict__ mpos,
                                            float* __restrict__ out) {
    const int c = blockIdx.x, tid = threadIdx.x;
    const int w = tid >> 5, lane = tid & 31;

    float* s_part = (float*)(smu + 131072);
    float* s_red  = (float*)(smu + 192512);
    int*   s_list = (int*)(smu + 193024);
    int*   s_wcnt = (int*)(smu + 197120);
    int*   s_cnt  = (int*)(smu + 197152);

    // ---- ordered index list for class c ----
    const int SEG = NI / 8;
    const int base = w * SEG;
    const int4* lab4 = (const int4*)labels;
    int cnt = 0;
    for (int it = 0; it < SEG / 128; it++) {
        int4 v = lab4[(base >> 2) + it * 32 + lane];
        cnt += (v.x == c) + (v.y == c) + (v.z == c) + (v.w == c);
    }
#pragma unroll
    for (int o = 16; o; o >>= 1) cnt += __shfl_xor_sync(0xffffffffu, cnt, o);
    if (lane == 0) s_wcnt[w] = cnt;
    __syncthreads();
    if (tid == 0) {
        int t = 0;
        for (int ww = 0; ww < 8; ww++) { int v = s_wcnt[ww]; s_wcnt[ww] = t; t += v; }
        *s_cnt = t;
    }
    __syncthreads();
    int off = s_wcnt[w];
    for (int it = 0; it < SEG / 128; it++) {
        int gidx = base + it * 128 + lane * 4;
        int4 v = lab4[gidx >> 2];
        int m0 = (v.x == c), m1 = (v.y == c), m2 = (v.z == c), m3 = (v.w == c);
        int nm = m0 + m1 + m2 + m3;
        int x = nm;
#pragma unroll
        for (int o = 1; o < 32; o <<= 1) {
            int y = __shfl_up_sync(0xffffffffu, x, o);
            if (lane >= o) x += y;
        }
        int p2 = off + x - nm;
        if (m0) { s_list[p2 < 1024 ? p2 : 1023] = gidx + 0; p2++; }
        if (m1) { s_list[p2 < 1024 ? p2 : 1023] = gidx + 1; p2++; }
        if (m2) { s_list[p2 < 1024 ? p2 : 1023] = gidx + 2; p2++; }
        if (m3) { s_list[p2 < 1024 ? p2 : 1023] = gidx + 3; p2++; }
        off += __shfl_sync(0xffffffffu, x, 31);
    }
    __syncthreads();

    const int n = *s_cnt < 1024 ? *s_cnt : 1024;

    // ---- warm ring buf0 with rows 0..7 (self-sliced: thread copies its own bytes) ----
    const uint32_t ring0 = smem_u32(smu) + tid * 16;
#pragma unroll
    for (int r = 0; r < 8; r++) {
        if (r < n) {
            const float* src = X + (size_t)s_list[r] * DIM + tid * 4;
            CPA16(ring0 + r * 8192, src);
            CPA16(ring0 + r * 8192 + 4096, src + 1024);
        }
    }
    CPCOMMIT();

    // ---- bank to registers ----
    const ulonglong2* memU = (const ulonglong2*)mem + (size_t)c * BK * (DIM / 4);
    ulonglong2 br[BK][2];
#pragma unroll
    for (int j = 0; j < BK; j++) {
        br[j][0] = memU[j * 512 + tid];
        br[j][1] = memU[j * 512 + 256 + tid];
    }

#define REDROWS(CNT, ROFF)                                                    \
    for (int rid = w; rid < (CNT); rid += 8) {                                \
        const float4* rp = (const float4*)(s_part + rid * 256);               \
        float4 a0 = rp[lane], a1 = rp[lane + 32];                             \
        float v = (a0.x + a0.y) + (a0.z + a0.w) + (a1.x + a1.y) + (a1.z + a1.w); \
        _Pragma("unroll") for (int o = 16; o; o >>= 1)                        \
            v += __shfl_xor_sync(0xffffffffu, v, o);                          \
        if (lane == 0) s_red[(ROFF) + rid] = v;                               \
    }

    // ---- prologue: bank norms ----
#pragma unroll
    for (int j = 0; j < BK; j++)
        s_part[j * 256 + tid] = pdot(br[j][0], br[j][1], br[j][0], br[j][1]);
    __syncthreads();
    REDROWS(10, 0);
    __syncthreads();
    float bn[BK];
#pragma unroll
    for (int j = 0; j < BK; j++) bn[j] = s_red[j];

    // ---- chunked scan ----
    int p = mpos[c];
    const int nch = (n + 7) >> 3;
    for (int ch = 0; ch < nch; ch++) {
        const int s0 = ch << 3;
        int cl = n - s0; if (cl > 8) cl = 8;
        const int buf = ch & 1;

        CPWAIT0();   // ring[buf] complete (self-copied bytes -> no bar needed)
        ulonglong2 xr[8][2];
        {
            const char* rb = smu + buf * 65536 + tid * 16;
#pragma unroll
            for (int r = 0; r < 8; r++) {
                xr[r][0] = *(const ulonglong2*)(rb + r * 8192);
                xr[r][1] = *(const ulonglong2*)(rb + r * 8192 + 4096);
            }
        }
        // prefetch next chunk into ring[buf^1]
        {
            const uint32_t rn = smem_u32(smu) + (buf ^ 1) * 65536 + tid * 16;
#pragma unroll
            for (int r = 0; r < 8; r++) {
                int g = s0 + 8 + r;
                if (g < n) {
                    const float* src = X + (size_t)s_list[g] * DIM + tid * 4;
                    CPA16(rn + r * 8192, src);
                    CPA16(rn + r * 8192 + 4096, src + 1024);
                }
            }
            CPCOMMIT();
        }

        // pass1: D rows t=0..5 (row id t*10+j)
#pragma unroll
        for (int t = 0; t < 6; t++)
#pragma unroll
            for (int j = 0; j < BK; j++)
                s_part[(t * 10 + j) * 256 + tid] =
                    pdot(br[j][0], br[j][1], xr[t][0], xr[t][1]);
        __syncthreads();
        REDROWS(60, 0);
        __syncthreads();

        // pass2: D t=6,7 (rows 0..19 -> red 60..79), pairs (rows 20..47 ->
        // red 80..107), norms (rows 48..55 -> red 108..115)
#pragma unroll
        for (int t = 6; t < 8; t++)
#pragma unroll
            for (int j = 0; j < BK; j++)
                s_part[((t - 6) * 10 + j) * 256 + tid] =
                    pdot(br[j][0], br[j][1], xr[t][0], xr[t][1]);
        {
            int k = 20;
#pragma unroll
            for (int t = 1; t < 8; t++)
#pragma unroll
                for (int i = 0; i < t; i++) {
                    s_part[k * 256 + tid] =
                        pdot(xr[i][0], xr[i][1], xr[t][0], xr[t][1]);
                    k++;
                }
        }
#pragma unroll
        for (int t = 0; t < 8; t++)
            s_part[(48 + t) * 256 + tid] =
                pdot(xr[t][0], xr[t][1], xr[t][0], xr[t][1]);
        __syncthreads();
        REDROWS(56, 60);
        __syncthreads();

        // scalar recurrence (redundant on all threads; broadcast LDS)
        int own[BK];
#pragma unroll
        for (int j = 0; j < BK; j++) own[j] = -1;
        for (int t = 0; t < cl; t++) {
            const int tri = 80 + ((t * (t - 1)) >> 1);
            const float xx = s_red[108 + t];
            int slot;
            if (p < BK) {
                slot = p; p++;
            } else {
                float dd[BK];
#pragma unroll
                for (int j = 0; j < BK; j++) {
                    int oj = own[j];
                    int idx = (oj < 0) ? (t * 10 + j) : (tri + oj);
                    // +|x_t|^2 dropped: constant across j, argmax-invariant
                    dd[j] = fmaf(-2.f, s_red[idx], bn[j]);
                }
                float mx = dd[0];
#pragma unroll
                for (int j = 1; j < BK; j++) mx = fmaxf(mx, dd[j]);
                slot = BK - 1;
#pragma unroll
                for (int j = BK - 1; j >= 0; j--) slot = (dd[j] == mx) ? j : slot;
            }
#pragma unroll
            for (int j = 0; j < BK; j++) {
                bn[j]  = (slot == j) ? xx : bn[j];
                own[j] = (slot == j) ? t  : own[j];
            }
        }

        // apply chunk writes to register bank (from ring[buf], own bytes)
        {
            const char* rb = smu + buf * 65536 + tid * 16;
#pragma unroll
            for (int j = 0; j < BK; j++) {
                int oj = own[j];
                if (oj >= 0) {
                    br[j][0] = *(const ulonglong2*)(rb + oj * 8192);
                    br[j][1] = *(const ulonglong2*)(rb + oj * 8192 + 4096);
                }
            }
        }
        // next loop's post-pass1 barrier orders s_red reads vs next reduce1
    }

    // ---- epilogue (out+16385 only 4B-aligned -> scalar stores) ----
    float* om = out + (NI + 1) + (size_t)c * BK * DIM;
#pragma unroll
    for (int j = 0; j < BK; j++) {
        float f0, f1, f2, f3;
        UNPACK2(f0, f1, br[j][0].x); UNPACK2(f2, f3, br[j][0].y);
        int d0 = j * DIM + tid * 4;
        om[d0 + 0] = f0; om[d0 + 1] = f1; om[d0 + 2] = f2; om[d0 + 3] = f3;
        UNPACK2(f0, f1, br[j][1].x); UNPACK2(f2, f3, br[j][1].y);
        int d1 = j * DIM + 1024 + tid * 4;
        om[d1 + 0] = f0; om[d1 + 1] = f1; om[d1 + 2] = f2; om[d1 + 3] = f3;
    }
    if (tid == 0) out[(NI + 1) + (size_t)NC * BK * DIM + c] = (float)p;
}

// ---------------------------------------------------------------------------
__global__ void __launch_bounds__(256, 1)
k_fused(const float* __restrict__ X, const int* __restrict__ labels,
        const float* __restrict__ mem, const int* __restrict__ mpos,
        float* __restrict__ out) {
    extern __shared__ char smdyn[];
    if (blockIdx.x < NC)
        update_path(smdyn, X, labels, mem, mpos, out);
    else
        gemm_path(smdyn, X, labels, out, blockIdx.x - NC);
}

// ---------------------------------------------------------------------------
// Fixup: exact fp32 re-check of near-tie instances; last block writes acc.
// ---------------------------------------------------------------------------
__global__ void __launch_bounds__(256) k_fixup(const float* __restrict__ X,
                                               const int* __restrict__ labels,
                                               float* __restrict__ out) {
    const int tid = threadIdx.x, w = tid >> 5, lane = tid & 31;
    __shared__ float ssc[NC];
    const int nfix = g_nfix < NI ? g_nfix : NI;
    for (int idx = blockIdx.x; idx < nfix; idx += gridDim.x) {
        const int gi = g_fix[idx];
        const float4* x4 = (const float4*)(X + (size_t)gi * DIM);
        for (int c = w; c < NC; c += 8) {
            const float4* m4 = (const float4*)(g_mmean + (size_t)c * DIM);
            float s = 0.f;
#pragma unroll
            for (int k = 0; k < 16; k++) {
                float4 a = x4[k * 32 + lane];
                float4 b = m4[k * 32 + lane];
                s += a.x * b.x + a.y * b.y + a.z * b.z + a.w * b.w;
            }
#pragma unroll
            for (int o = 16; o; o >>= 1) s += __shfl_xor_sync(0xffffffffu, s, o);
            if (lane == 0) ssc[c] = g_bias[c] - s;
        }
        __syncthreads();
        if (tid == 0) {
            float best = 3e38f;
            int bc = 0;
            for (int cc = 0; cc < NC; cc++) {
                float v = ssc[cc];
                if (v < best) { best = v; bc = cc; }
            }
            int oldbc = (int)out[gi];
            if (oldbc != bc) {
                int lab = labels[gi];
                atomicAdd(&g_count, (bc == lab) - (oldbc == lab));
                out[gi] = (float)bc;
            }
        }
        __syncthreads();
    }
    __syncthreads();
    if (tid == 0) {
        __threadfence();
        int tk = atomicAdd(&g_tick, 1);
        if (tk == (int)gridDim.x - 1)
            out[NI] = (float)atomicAdd(&g_count, 0) * (1.0f / NI);
    }
}

// ---------------------------------------------------------------------------
extern "C" void kernel_launch(void* const* d_in, const int* in_sizes, int n_in,
                              void* d_out, int out_size) {
    const float* X      = (const float*)d_in[0];
    const int*   labels = (const int*)d_in[1];
    const float* mem    = (const float*)d_in[2];
    const int*   mpos   = (const int*)d_in[3];
    float* out = (float*)d_out;

    static bool init = false;
    if (!init) {
        init = true;
        cudaFuncSetAttribute(k_fused, cudaFuncAttributeMaxDynamicSharedMemorySize, SMEM_FUSED);
    }

    k_mean<<<NCP, 256>>>(mem);
    k_fused<<<NC + NI / BMG, 256, SMEM_FUSED>>>(X, labels, mem, mpos, out);
    k_fixup<<<296, 256>>>(X, labels, out);
}

// round 12
// speedup vs baseline: 1.0862x; 1.0862x over previous
#include <cuda_runtime.h>
#include <cuda_bf16.h>
#include <cstdint>

#define NC   81
#define NCP  96
#define BK   10
#define DIM  2048
#define NI   16384
#define NT   64
#define BMG  128
#define THR  0.5f

__device__ int   g_count;
__device__ int   g_nfix;
__device__ int   g_tick;
__device__ int   g_fix[NI];
__device__ unsigned g_fixm[NI * 3];
__device__ float g_bias[NCP];
__device__ float g_mmean[NC * DIM];
__device__ __align__(16) unsigned short g_mbf[NT * NCP * 64];

__device__ __forceinline__ uint32_t smem_u32(const void* p) {
    uint32_t a;
    asm("{ .reg .u64 t; cvta.to.shared.u64 t, %1; cvt.u32.u64 %0, t; }" : "=r"(a) : "l"(p));
    return a;
}

#define LDSM_X4(r0, r1, r2, r3, addr)                                         \
    asm volatile("ldmatrix.sync.aligned.m8n8.x4.shared.b16 {%0,%1,%2,%3}, [%4];" \
                 : "=r"(r0), "=r"(r1), "=r"(r2), "=r"(r3) : "r"(addr))

#define MMA16816(d, a, b0v, b1v)                                              \
    asm volatile("mma.sync.aligned.m16n8k16.row.col.f32.bf16.bf16.f32 "       \
                 "{%0,%1,%2,%3},{%4,%5,%6,%7},{%8,%9},{%0,%1,%2,%3};"         \
                 : "+f"((d)[0]), "+f"((d)[1]), "+f"((d)[2]), "+f"((d)[3])     \
                 : "r"((a)[0]), "r"((a)[1]), "r"((a)[2]), "r"((a)[3]),        \
                   "r"(b0v), "r"(b1v))

#define FMA2(d, a, b, c) asm("fma.rn.f32x2 %0, %1, %2, %3;" : "=l"(d) : "l"(a), "l"(b), "l"(c))
#define UNPACK2(lo, hi, v) asm("mov.b64 {%0, %1}, %2;" : "=f"(lo), "=f"(hi) : "l"(v))

#define CPA16(dst, src) asm volatile("cp.async.cg.shared.global [%0], [%1], 16;" :: "r"(dst), "l"(src) : "memory")
#define CPCOMMIT()      asm volatile("cp.async.commit_group;" ::: "memory")
#define CPWAIT0()       asm volatile("cp.async.wait_group 0;" ::: "memory")

__device__ __forceinline__ unsigned pkbf(__nv_bfloat16 a, __nv_bfloat16 b) {
    return ((unsigned)__bfloat16_as_ushort(b) << 16) | (unsigned)__bfloat16_as_ushort(a);
}

__device__ __forceinline__ float pdot(ulonglong2 A0, ulonglong2 A1,
                                      ulonglong2 B0, ulonglong2 B1) {
    unsigned long long pa = 0ull;
    FMA2(pa, A0.x, B0.x, pa); FMA2(pa, A0.y, B0.y, pa);
    FMA2(pa, A1.x, B1.x, pa); FMA2(pa, A1.y, B1.y, pa);
    float lo, hi; UNPACK2(lo, hi, pa);
    return lo + hi;
}

// ---------------------------------------------------------------------------
// Kernel 1: class means -> fp32 plane + bf16 hi/lo planes + bias; zero pads.
// ---------------------------------------------------------------------------
__global__ void k_mean(const float* __restrict__ mem) {
    int c = blockIdx.x, tid = threadIdx.x;
    if (c == 0 && tid == 0) { g_count = 0; g_nfix = 0; g_tick = 0; }
    if (c >= NC) {
        for (int d = tid; d < DIM; d += 256) {
            int tt = d >> 5, j = d & 31;
            g_mbf[(tt * NCP + c) * 64 + j] = 0;
            g_mbf[(tt * NCP + c) * 64 + 32 + j] = 0;
        }
        return;
    }
    float part = 0.f;
    for (int d = tid; d < DIM; d += 256) {
        float s = 0.f;
#pragma unroll
        for (int b = 0; b < BK; b++) s += mem[(size_t)(c * BK + b) * DIM + d];
        float m = s * (1.0f / BK);
        g_mmean[c * DIM + d] = m;
        __nv_bfloat16 hi = __float2bfloat16_rn(m);
        __nv_bfloat16 lo = __float2bfloat16_rn(m - __bfloat162float(hi));
        int tt = d >> 5, j = d & 31;
        g_mbf[(tt * NCP + c) * 64 + j] = __bfloat16_as_ushort(hi);
        g_mbf[(tt * NCP + c) * 64 + 32 + j] = __bfloat16_as_ushort(lo);
        part += m * m;
    }
#pragma unroll
    for (int o = 16; o; o >>= 1) part += __shfl_xor_sync(0xffffffffu, part, o);
    __shared__ float rb[8];
    if ((tid & 31) == 0) rb[tid >> 5] = part;
    __syncthreads();
    if (tid == 0) {
        float t = 0.f;
#pragma unroll
        for (int w = 0; w < 8; w++) t += rb[w];
        g_bias[c] = 0.5f * t;
    }
}

// ---------------------------------------------------------------------------
// GEMM path (blocks >= 81): 2-product HMMA (x_hi * [m_hi | m_lo]).
// A tile: 128 rows x 64B (hi only). B tile: 96 rows x 128B [hi|lo].
// Near-ties (margin < THR) flagged with a candidate-class bitmask.
// ---------------------------------------------------------------------------
#define STAGE 20480
#define SMEM_FUSED 197632

__device__ __forceinline__ void gemm_path(char* sm, const float* __restrict__ X,
                                          const int* __restrict__ labels,
                                          float* __restrict__ out, int gb) {
    const uint32_t sb = smem_u32(sm);
    const int tid = threadIdx.x, wid = tid >> 5, lane = tid & 31;
    const int i0 = gb * BMG;
    const int mwarp = wid & 3, nwarp = wid >> 2;

    const int r = tid >> 1, h = tid & 1;
    const float* xrow = X + (size_t)(i0 + r) * DIM + h * 16;
    const uint4* mb4 = (const uint4*)g_mbf;

    float d[2][6][4];
#pragma unroll
    for (int a = 0; a < 2; a++)
#pragma unroll
        for (int b = 0; b < 6; b++)
#pragma unroll
            for (int e = 0; e < 4; e++) d[a][b][e] = 0.f;

    float4 cur0, cur1, cur2, cur3;
#define GLOAD(t)                                                    \
    {   const float4* p4 = (const float4*)(xrow + (t) * 32);        \
        cur0 = p4[0]; cur1 = p4[1]; cur2 = p4[2]; cur3 = p4[3]; }

#define GSTORE(t, buf)                                                          \
    {   float f[16];                                                            \
        *(float4*)(f + 0) = cur0; *(float4*)(f + 4) = cur1;                     \
        *(float4*)(f + 8) = cur2; *(float4*)(f + 12) = cur3;                    \
        unsigned hw[8];                                                         \
        _Pragma("unroll") for (int j = 0; j < 8; j++)                           \
            hw[j] = pkbf(__float2bfloat16_rn(f[2 * j]),                         \
                         __float2bfloat16_rn(f[2 * j + 1]));                    \
        char* Ab = sm + (buf) * STAGE;                                          \
        const int rx = r & 3;                                                   \
        *(uint4*)(Ab + r * 64 + 16 * ((2 * h + 0) ^ rx)) = make_uint4(hw[0], hw[1], hw[2], hw[3]); \
        *(uint4*)(Ab + r * 64 + 16 * ((2 * h + 1) ^ rx)) = make_uint4(hw[4], hw[5], hw[6], hw[7]); \
        char* Bb = Ab + 8192;                                                   \
        _Pragma("unroll") for (int q = 0; q < 3; q++) {                         \
            int g = tid + q * 256;                                              \
            int brow = g >> 3, bch = g & 7;                                     \
            *(uint4*)(Bb + brow * 128 + 16 * (bch ^ (brow & 7))) = mb4[(t) * 768 + g]; \
        }                                                                       \
    }

    GLOAD(0);
    GSTORE(0, 0);

    for (int t = 0; t < NT; t++) {
        const int buf = t & 1;
        if (t + 1 < NT) GLOAD(t + 1);
        __syncthreads();

        const uint32_t Abase = sb + buf * STAGE;
        const uint32_t Bbase = Abase + 8192;

        uint32_t afr[2][2][4];   // [mt][s][4]
#pragma unroll
        for (int mt = 0; mt < 2; mt++) {
            int rowA = mwarp * 32 + mt * 16 + (lane & 15);
            uint32_t rbase = Abase + rowA * 64;
            int rx = rowA & 3;
#pragma unroll
            for (int s = 0; s < 2; s++) {
                int ch = s * 2 + (lane >> 4);
                uint32_t ad = rbase + 16 * (ch ^ rx);
                LDSM_X4(afr[mt][s][0], afr[mt][s][1],
                        afr[mt][s][2], afr[mt][s][3], ad);
            }
        }

#pragma unroll
        for (int pp = 0; pp < 2; pp++) {      // bpl = pp (m hi / m lo)
#pragma unroll
            for (int np = 0; np < 3; np++) {
                int rowB = nwarp * 48 + np * 16 + (lane & 15);
                uint32_t rbase = Bbase + rowB * 128;
                int rx = rowB & 7;
#pragma unroll
                for (int s = 0; s < 2; s++) {
                    int ch = pp * 4 + s * 2 + (lane >> 4);
                    uint32_t bd = rbase + 16 * (ch ^ rx);
                    uint32_t b0, b1, b2, b3;
                    LDSM_X4(b0, b1, b2, b3, bd);
#pragma unroll
                    for (int mt = 0; mt < 2; mt++) {
                        MMA16816(d[mt][np * 2 + 0], afr[mt][s], b0, b2);
                        MMA16816(d[mt][np * 2 + 1], afr[mt][s], b1, b3);
                    }
                }
            }
        }
        __syncthreads();
        if (t + 1 < NT) GSTORE(t + 1, (t + 1) & 1);
    }
    __syncthreads();

    float* sc = (float*)sm;
#pragma unroll
    for (int mt = 0; mt < 2; mt++) {
#pragma unroll
        for (int np = 0; np < 3; np++)
#pragma unroll
            for (int hh = 0; hh < 2; hh++) {
                int row0 = mwarp * 32 + mt * 16 + (lane >> 2);
                int col0 = nwarp * 48 + np * 16 + hh * 8 + 2 * (lane & 3);
                const float* dd = d[mt][np * 2 + hh];
                if (col0 < NC) sc[row0 * 97 + col0] = g_bias[col0] - dd[0];
                if (col0 + 1 < NC) sc[row0 * 97 + col0 + 1] = g_bias[col0 + 1] - dd[1];
                if (col0 < NC) sc[(row0 + 8) * 97 + col0] = g_bias[col0] - dd[2];
                if (col0 + 1 < NC) sc[(row0 + 8) * 97 + col0 + 1] = g_bias[col0 + 1] - dd[3];
            }
    }
    __syncthreads();

    if (tid < BMG) {
        int gi = i0 + tid;
        const float* row = sc + tid * 97;
        float best = 3e38f;
        int bc = 0;
#pragma unroll 4
        for (int cc = 0; cc < NC; cc++) {
            float v = row[cc];
            if (v < best) { best = v; bc = cc; }
        }
        out[gi] = (float)bc;
        // candidate bitmask: classes within THR of best
        unsigned mk0 = 0, mk1 = 0, mk2 = 0;
        int ncand = 0;
        float lim = best + THR;
#pragma unroll 4
        for (int cc = 0; cc < NC; cc++) {
            if (row[cc] < lim) {
                ncand++;
                if (cc < 32) mk0 |= 1u << cc;
                else if (cc < 64) mk1 |= 1u << (cc - 32);
                else mk2 |= 1u << (cc - 64);
            }
        }
        if (ncand > 1) {
            int slot = atomicAdd(&g_nfix, 1);
            if (slot < NI) {
                g_fix[slot] = gi;
                g_fixm[slot * 3 + 0] = mk0;
                g_fixm[slot * 3 + 1] = mk1;
                g_fixm[slot * 3 + 2] = mk2;
            }
        }
        unsigned bal = __ballot_sync(0xffffffffu, bc == labels[gi]);
        if ((tid & 31) == 0) atomicAdd(&g_count, __popc(bal));
    }
}

// ---------------------------------------------------------------------------
// Update path (blocks 0..80): CHUNKED sequential update, T=8 (R10 structure).
// ---------------------------------------------------------------------------
__device__ __forceinline__ void update_path(char* smu, const float* __restrict__ X,
                                            const int* __restrict__ labels,
                                            const float* __restrict__ mem,
                                            const int* __restrict__ mpos,
                                            float* __restrict__ out) {
    const int c = blockIdx.x, tid = threadIdx.x;
    const int w = tid >> 5, lane = tid & 31;

    float* s_part = (float*)(smu + 131072);
    float* s_red  = (float*)(smu + 192512);
    int*   s_list = (int*)(smu + 193024);
    int*   s_wcnt = (int*)(smu + 197120);
    int*   s_cnt  = (int*)(smu + 197152);

    const int SEG = NI / 8;
    const int base = w * SEG;
    const int4* lab4 = (const int4*)labels;
    int cnt = 0;
    for (int it = 0; it < SEG / 128; it++) {
        int4 v = lab4[(base >> 2) + it * 32 + lane];
        cnt += (v.x == c) + (v.y == c) + (v.z == c) + (v.w == c);
    }
#pragma unroll
    for (int o = 16; o; o >>= 1) cnt += __shfl_xor_sync(0xffffffffu, cnt, o);
    if (lane == 0) s_wcnt[w] = cnt;
    __syncthreads();
    if (tid == 0) {
        int t = 0;
        for (int ww = 0; ww < 8; ww++) { int v = s_wcnt[ww]; s_wcnt[ww] = t; t += v; }
        *s_cnt = t;
    }
    __syncthreads();
    int off = s_wcnt[w];
    for (int it = 0; it < SEG / 128; it++) {
        int gidx = base + it * 128 + lane * 4;
        int4 v = lab4[gidx >> 2];
        int m0 = (v.x == c), m1 = (v.y == c), m2 = (v.z == c), m3 = (v.w == c);
        int nm = m0 + m1 + m2 + m3;
        int x = nm;
#pragma unroll
        for (int o = 1; o < 32; o <<= 1) {
            int y = __shfl_up_sync(0xffffffffu, x, o);
            if (lane >= o) x += y;
        }
        int p2 = off + x - nm;
        if (m0) { s_list[p2 < 1024 ? p2 : 1023] = gidx + 0; p2++; }
        if (m1) { s_list[p2 < 1024 ? p2 : 1023] = gidx + 1; p2++; }
        if (m2) { s_list[p2 < 1024 ? p2 : 1023] = gidx + 2; p2++; }
        if (m3) { s_list[p2 < 1024 ? p2 : 1023] = gidx + 3; p2++; }
        off += __shfl_sync(0xffffffffu, x, 31);
    }
    __syncthreads();

    const int n = *s_cnt < 1024 ? *s_cnt : 1024;

    const uint32_t ring0 = smem_u32(smu) + tid * 16;
#pragma unroll
    for (int r = 0; r < 8; r++) {
        if (r < n) {
            const float* src = X + (size_t)s_list[r] * DIM + tid * 4;
            CPA16(ring0 + r * 8192, src);
            CPA16(ring0 + r * 8192 + 4096, src + 1024);
        }
    }
    CPCOMMIT();

    const ulonglong2* memU = (const ulonglong2*)mem + (size_t)c * BK * (DIM / 4);
    ulonglong2 br[BK][2];
#pragma unroll
    for (int j = 0; j < BK; j++) {
        br[j][0] = memU[j * 512 + tid];
        br[j][1] = memU[j * 512 + 256 + tid];
    }

#define REDROWS(CNT, ROFF)                                                    \
    for (int rid = w; rid < (CNT); rid += 8) {                                \
        const float4* rp = (const float4*)(s_part + rid * 256);               \
        float4 a0 = rp[lane], a1 = rp[lane + 32];                             \
        float v = (a0.x + a0.y) + (a0.z + a0.w) + (a1.x + a1.y) + (a1.z + a1.w); \
        _Pragma("unroll") for (int o = 16; o; o >>= 1)                        \
            v += __shfl_xor_sync(0xffffffffu, v, o);                          \
        if (lane == 0) s_red[(ROFF) + rid] = v;                               \
    }

#pragma unroll
    for (int j = 0; j < BK; j++)
        s_part[j * 256 + tid] = pdot(br[j][0], br[j][1], br[j][0], br[j][1]);
    __syncthreads();
    REDROWS(10, 0);
    __syncthreads();
    float bn[BK];
#pragma unroll
    for (int j = 0; j < BK; j++) bn[j] = s_red[j];

    int p = mpos[c];
    const int nch = (n + 7) >> 3;
    for (int ch = 0; ch < nch; ch++) {
        const int s0 = ch << 3;
        int cl = n - s0; if (cl > 8) cl = 8;
        const int buf = ch & 1;

        CPWAIT0();
        ulonglong2 xr[8][2];
        {
            const char* rb = smu + buf * 65536 + tid * 16;
#pragma unroll
            for (int r = 0; r < 8; r++) {
                xr[r][0] = *(const ulonglong2*)(rb + r * 8192);
                xr[r][1] = *(const ulonglong2*)(rb + r * 8192 + 4096);
            }
        }
        {
            const uint32_t rn = smem_u32(smu) + (buf ^ 1) * 65536 + tid * 16;
#pragma unroll
            for (int r = 0; r < 8; r++) {
                int g = s0 + 8 + r;
                if (g < n) {
                    const float* src = X + (size_t)s_list[g] * DIM + tid * 4;
                    CPA16(rn + r * 8192, src);
                    CPA16(rn + r * 8192 + 4096, src + 1024);
                }
            }
            CPCOMMIT();
        }

#pragma unroll
        for (int t = 0; t < 6; t++)
#pragma unroll
            for (int j = 0; j < BK; j++)
                s_part[(t * 10 + j) * 256 + tid] =
                    pdot(br[j][0], br[j][1], xr[t][0], xr[t][1]);
        __syncthreads();
        REDROWS(60, 0);
        __syncthreads();

#pragma unroll
        for (int t = 6; t < 8; t++)
#pragma unroll
            for (int j = 0; j < BK; j++)
                s_part[((t - 6) * 10 + j) * 256 + tid] =
                    pdot(br[j][0], br[j][1], xr[t][0], xr[t][1]);
        {
            int k = 20;
#pragma unroll
            for (int t = 1; t < 8; t++)
#pragma unroll
                for (int i = 0; i < t; i++) {
                    s_part[k * 256 + tid] =
                        pdot(xr[i][0], xr[i][1], xr[t][0], xr[t][1]);
                    k++;
                }
        }
#pragma unroll
        for (int t = 0; t < 8; t++)
            s_part[(48 + t) * 256 + tid] =
                pdot(xr[t][0], xr[t][1], xr[t][0], xr[t][1]);
        __syncthreads();
        REDROWS(56, 60);
        __syncthreads();

        int own[BK];
#pragma unroll
        for (int j = 0; j < BK; j++) own[j] = -1;
        for (int t = 0; t < cl; t++) {
            const int tri = 80 + ((t * (t - 1)) >> 1);
            const float xx = s_red[108 + t];
            int slot;
            if (p < BK) {
                slot = p; p++;
            } else {
                float dd[BK];
#pragma unroll
                for (int j = 0; j < BK; j++) {
                    int oj = own[j];
                    int idx = (oj < 0) ? (t * 10 + j) : (tri + oj);
                    dd[j] = fmaf(-2.f, s_red[idx], bn[j]);
                }
                float mx = dd[0];
#pragma unroll
                for (int j = 1; j < BK; j++) mx = fmaxf(mx, dd[j]);
                slot = BK - 1;
#pragma unroll
                for (int j = BK - 1; j >= 0; j--) slot = (dd[j] == mx) ? j : slot;
            }
#pragma unroll
            for (int j = 0; j < BK; j++) {
                bn[j]  = (slot == j) ? xx : bn[j];
                own[j] = (slot == j) ? t  : own[j];
            }
        }

        {
            const char* rb = smu + buf * 65536 + tid * 16;
#pragma unroll
            for (int j = 0; j < BK; j++) {
                int oj = own[j];
                if (oj >= 0) {
                    br[j][0] = *(const ulonglong2*)(rb + oj * 8192);
                    br[j][1] = *(const ulonglong2*)(rb + oj * 8192 + 4096);
                }
            }
        }
    }

    float* om = out + (NI + 1) + (size_t)c * BK * DIM;
#pragma unroll
    for (int j = 0; j < BK; j++) {
        float f0, f1, f2, f3;
        UNPACK2(f0, f1, br[j][0].x); UNPACK2(f2, f3, br[j][0].y);
        int d0 = j * DIM + tid * 4;
        om[d0 + 0] = f0; om[d0 + 1] = f1; om[d0 + 2] = f2; om[d0 + 3] = f3;
        UNPACK2(f0, f1, br[j][1].x); UNPACK2(f2, f3, br[j][1].y);
        int d1 = j * DIM + 1024 + tid * 4;
        om[d1 + 0] = f0; om[d1 + 1] = f1; om[d1 + 2] = f2; om[d1 + 3] = f3;
    }
    if (tid == 0) out[(NI + 1) + (size_t)NC * BK * DIM + c] = (float)p;
}

// ---------------------------------------------------------------------------
__global__ void __launch_bounds__(256, 1)
k_fused(const float* __restrict__ X, const int* __restrict__ labels,
        const float* __restrict__ mem, const int* __restrict__ mpos,
        float* __restrict__ out) {
    extern __shared__ char smdyn[];
    if (blockIdx.x < NC)
        update_path(smdyn, X, labels, mem, mpos, out);
    else
        gemm_path(smdyn, X, labels, out, blockIdx.x - NC);
}

// ---------------------------------------------------------------------------
// Fixup: exact fp32 re-check of the CANDIDATE classes only (bitmask-guided).
// Last block finalizes accuracy.
// ---------------------------------------------------------------------------
__global__ void __launch_bounds__(256) k_fixup(const float* __restrict__ X,
                                               const int* __restrict__ labels,
                                               float* __restrict__ out) {
    const int tid = threadIdx.x, w = tid >> 5, lane = tid & 31;
    __shared__ int   s_cand[NC];
    __shared__ float s_sc[NC];
    __shared__ int   s_nc;
    const int nfix = g_nfix < NI ? g_nfix : NI;
    for (int idx = blockIdx.x; idx < nfix; idx += gridDim.x) {
        const int gi = g_fix[idx];
        if (tid == 0) {
            int k = 0;
            unsigned m0 = g_fixm[idx * 3], m1 = g_fixm[idx * 3 + 1], m2 = g_fixm[idx * 3 + 2];
            for (int cc = 0; cc < NC; cc++) {
                unsigned mw = (cc < 32) ? m0 : (cc < 64) ? m1 : m2;
                if ((mw >> (cc & 31)) & 1u) s_cand[k++] = cc;
            }
            s_nc = k;
        }
        __syncthreads();
        const int ncd = s_nc;
        const float4* x4 = (const float4*)(X + (size_t)gi * DIM);
        for (int ci = w; ci < ncd; ci += 8) {
            int c = s_cand[ci];
            const float4* m4 = (const float4*)(g_mmean + (size_t)c * DIM);
            float s = 0.f;
#pragma unroll
            for (int k = 0; k < 16; k++) {
                float4 a = x4[k * 32 + lane];
                float4 b = m4[k * 32 + lane];
                s += a.x * b.x + a.y * b.y + a.z * b.z + a.w * b.w;
            }
#pragma unroll
            for (int o = 16; o; o >>= 1) s += __shfl_xor_sync(0xffffffffu, s, o);
            if (lane == 0) s_sc[ci] = g_bias[c] - s;
        }
        __syncthreads();
        if (tid == 0) {
            float best = 3e38f;
            int bc = 0;
            for (int ci = 0; ci < ncd; ci++) {
                float v = s_sc[ci];
                if (v < best) { best = v; bc = s_cand[ci]; }
            }
            int oldbc = (int)out[gi];
            if (oldbc != bc) {
                int lab = labels[gi];
                atomicAdd(&g_count, (bc == lab) - (oldbc == lab));
                out[gi] = (float)bc;
            }
        }
        __syncthreads();
    }
    __syncthreads();
    if (tid == 0) {
        __threadfence();
        int tk = atomicAdd(&g_tick, 1);
        if (tk == (int)gridDim.x - 1)
            out[NI] = (float)atomicAdd(&g_count, 0) * (1.0f / NI);
    }
}

// ---------------------------------------------------------------------------
extern "C" void kernel_launch(void* const* d_in, const int* in_sizes, int n_in,
                              void* d_out, int out_size) {
    const float* X      = (const float*)d_in[0];
    const int*   labels = (const int*)d_in[1];
    const float* mem    = (const float*)d_in[2];
    const int*   mpos   = (const int*)d_in[3];
    float* out = (float*)d_out;

    static bool init = false;
    if (!init) {
        init = true;
        cudaFuncSetAttribute(k_fused, cudaFuncAttributeMaxDynamicSharedMemorySize, SMEM_FUSED);
    }

    k_mean<<<NCP, 256>>>(mem);
    k_fused<<<NC + NI / BMG, 256, SMEM_FUSED>>>(X, labels, mem, mpos, out);
    k_fixup<<<296, 256>>>(X, labels, out);
}

// round 13
// speedup vs baseline: 1.0875x; 1.0012x over previous
#include <cuda_runtime.h>
#include <cuda_bf16.h>
#include <cstdint>

#define NC   81
#define NCP  96
#define BK   10
#define DIM  2048
#define NI   16384
#define NT   64
#define BMG  128
#define THR  0.5f

__device__ int   g_count;
__device__ int   g_nfix;
__device__ int   g_tick;
__device__ int   g_fix[NI];
__device__ unsigned g_fixm[NI * 3];
__device__ float g_bias[NCP];
__device__ float g_mmean[NC * DIM];
__device__ __align__(16) unsigned short g_mbf[NT * NCP * 64];

__device__ __forceinline__ uint32_t smem_u32(const void* p) {
    uint32_t a;
    asm("{ .reg .u64 t; cvta.to.shared.u64 t, %1; cvt.u32.u64 %0, t; }" : "=r"(a) : "l"(p));
    return a;
}

#define LDSM_X4(r0, r1, r2, r3, addr)                                         \
    asm volatile("ldmatrix.sync.aligned.m8n8.x4.shared.b16 {%0,%1,%2,%3}, [%4];" \
                 : "=r"(r0), "=r"(r1), "=r"(r2), "=r"(r3) : "r"(addr))

#define MMA16816(d, a, b0v, b1v)                                              \
    asm volatile("mma.sync.aligned.m16n8k16.row.col.f32.bf16.bf16.f32 "       \
                 "{%0,%1,%2,%3},{%4,%5,%6,%7},{%8,%9},{%0,%1,%2,%3};"         \
                 : "+f"((d)[0]), "+f"((d)[1]), "+f"((d)[2]), "+f"((d)[3])     \
                 : "r"((a)[0]), "r"((a)[1]), "r"((a)[2]), "r"((a)[3]),        \
                   "r"(b0v), "r"(b1v))

#define FMA2(d, a, b, c) asm("fma.rn.f32x2 %0, %1, %2, %3;" : "=l"(d) : "l"(a), "l"(b), "l"(c))
#define UNPACK2(lo, hi, v) asm("mov.b64 {%0, %1}, %2;" : "=f"(lo), "=f"(hi) : "l"(v))

#define CPA16(dst, src) asm volatile("cp.async.cg.shared.global [%0], [%1], 16;" :: "r"(dst), "l"(src) : "memory")
#define CPCOMMIT()      asm volatile("cp.async.commit_group;" ::: "memory")
#define CPWAIT0()       asm volatile("cp.async.wait_group 0;" ::: "memory")

__device__ __forceinline__ unsigned pkbf(__nv_bfloat16 a, __nv_bfloat16 b) {
    return ((unsigned)__bfloat16_as_ushort(b) << 16) | (unsigned)__bfloat16_as_ushort(a);
}

__device__ __forceinline__ float pdot(ulonglong2 A0, ulonglong2 A1,
                                      ulonglong2 B0, ulonglong2 B1) {
    unsigned long long pa = 0ull;
    FMA2(pa, A0.x, B0.x, pa); FMA2(pa, A0.y, B0.y, pa);
    FMA2(pa, A1.x, B1.x, pa); FMA2(pa, A1.y, B1.y, pa);
    float lo, hi; UNPACK2(lo, hi, pa);
    return lo + hi;
}

// ---------------------------------------------------------------------------
// Kernel 1: class means -> fp32 plane + bf16 hi/lo planes + bias; zero pads.
// ---------------------------------------------------------------------------
__global__ void k_mean(const float* __restrict__ mem) {
    int c = blockIdx.x, tid = threadIdx.x;
    if (c == 0 && tid == 0) { g_count = 0; g_nfix = 0; g_tick = 0; }
    if (c >= NC) {
        for (int d = tid; d < DIM; d += 256) {
            int tt = d >> 5, j = d & 31;
            g_mbf[(tt * NCP + c) * 64 + j] = 0;
            g_mbf[(tt * NCP + c) * 64 + 32 + j] = 0;
        }
        return;
    }
    float part = 0.f;
    for (int d = tid; d < DIM; d += 256) {
        float s = 0.f;
#pragma unroll
        for (int b = 0; b < BK; b++) s += mem[(size_t)(c * BK + b) * DIM + d];
        float m = s * (1.0f / BK);
        g_mmean[c * DIM + d] = m;
        __nv_bfloat16 hi = __float2bfloat16_rn(m);
        __nv_bfloat16 lo = __float2bfloat16_rn(m - __bfloat162float(hi));
        int tt = d >> 5, j = d & 31;
        g_mbf[(tt * NCP + c) * 64 + j] = __bfloat16_as_ushort(hi);
        g_mbf[(tt * NCP + c) * 64 + 32 + j] = __bfloat16_as_ushort(lo);
        part += m * m;
    }
#pragma unroll
    for (int o = 16; o; o >>= 1) part += __shfl_xor_sync(0xffffffffu, part, o);
    __shared__ float rb[8];
    if ((tid & 31) == 0) rb[tid >> 5] = part;
    __syncthreads();
    if (tid == 0) {
        float t = 0.f;
#pragma unroll
        for (int w = 0; w < 8; w++) t += rb[w];
        g_bias[c] = 0.5f * t;
    }
}

// ---------------------------------------------------------------------------
// GEMM path (blocks >= 81): 2-product HMMA (x_hi * [m_hi | m_lo]).
// A tile: 128 rows x 64B (hi only). B tile: 96 rows x 128B [hi|lo].
// Near-ties (margin < THR) flagged with a candidate-class bitmask.
// ---------------------------------------------------------------------------
#define STAGE 20480
#define SMEM_FUSED 197632

__device__ __forceinline__ void gemm_path(char* sm, const float* __restrict__ X,
                                          const int* __restrict__ labels,
                                          float* __restrict__ out, int gb) {
    const uint32_t sb = smem_u32(sm);
    const int tid = threadIdx.x, wid = tid >> 5, lane = tid & 31;
    const int i0 = gb * BMG;
    const int mwarp = wid & 3, nwarp = wid >> 2;

    const int r = tid >> 1, h = tid & 1;
    const float* xrow = X + (size_t)(i0 + r) * DIM + h * 16;
    const uint4* mb4 = (const uint4*)g_mbf;

    float d[2][6][4];
#pragma unroll
    for (int a = 0; a < 2; a++)
#pragma unroll
        for (int b = 0; b < 6; b++)
#pragma unroll
            for (int e = 0; e < 4; e++) d[a][b][e] = 0.f;

    float4 cur0, cur1, cur2, cur3;
#define GLOAD(t)                                                    \
    {   const float4* p4 = (const float4*)(xrow + (t) * 32);        \
        cur0 = p4[0]; cur1 = p4[1]; cur2 = p4[2]; cur3 = p4[3]; }

#define GSTORE(t, buf)                                                          \
    {   float f[16];                                                            \
        *(float4*)(f + 0) = cur0; *(float4*)(f + 4) = cur1;                     \
        *(float4*)(f + 8) = cur2; *(float4*)(f + 12) = cur3;                    \
        unsigned hw[8];                                                         \
        _Pragma("unroll") for (int j = 0; j < 8; j++)                           \
            hw[j] = pkbf(__float2bfloat16_rn(f[2 * j]),                         \
                         __float2bfloat16_rn(f[2 * j + 1]));                    \
        char* Ab = sm + (buf) * STAGE;                                          \
        const int rx = r & 3;                                                   \
        *(uint4*)(Ab + r * 64 + 16 * ((2 * h + 0) ^ rx)) = make_uint4(hw[0], hw[1], hw[2], hw[3]); \
        *(uint4*)(Ab + r * 64 + 16 * ((2 * h + 1) ^ rx)) = make_uint4(hw[4], hw[5], hw[6], hw[7]); \
        char* Bb = Ab + 8192;                                                   \
        _Pragma("unroll") for (int q = 0; q < 3; q++) {                         \
            int g = tid + q * 256;                                              \
            int brow = g >> 3, bch = g & 7;                                     \
            *(uint4*)(Bb + brow * 128 + 16 * (bch ^ (brow & 7))) = mb4[(t) * 768 + g]; \
        }                                                                       \
    }

    GLOAD(0);
    GSTORE(0, 0);

    for (int t = 0; t < NT; t++) {
        const int buf = t & 1;
        if (t + 1 < NT) GLOAD(t + 1);
        __syncthreads();

        const uint32_t Abase = sb + buf * STAGE;
        const uint32_t Bbase = Abase + 8192;

        uint32_t afr[2][2][4];   // [mt][s][4]
#pragma unroll
        for (int mt = 0; mt < 2; mt++) {
            int rowA = mwarp * 32 + mt * 16 + (lane & 15);
            uint32_t rbase = Abase + rowA * 64;
            int rx = rowA & 3;
#pragma unroll
            for (int s = 0; s < 2; s++) {
                int ch = s * 2 + (lane >> 4);
                uint32_t ad = rbase + 16 * (ch ^ rx);
                LDSM_X4(afr[mt][s][0], afr[mt][s][1],
                        afr[mt][s][2], afr[mt][s][3], ad);
            }
        }

#pragma unroll
        for (int pp = 0; pp < 2; pp++) {      // bpl = pp (m hi / m lo)
#pragma unroll
            for (int np = 0; np < 3; np++) {
                int rowB = nwarp * 48 + np * 16 + (lane & 15);
                uint32_t rbase = Bbase + rowB * 128;
                int rx = rowB & 7;
#pragma unroll
                for (int s = 0; s < 2; s++) {
                    int ch = pp * 4 + s * 2 + (lane >> 4);
                    uint32_t bd = rbase + 16 * (ch ^ rx);
                    uint32_t b0, b1, b2, b3;
                    LDSM_X4(b0, b1, b2, b3, bd);
#pragma unroll
                    for (int mt = 0; mt < 2; mt++) {
                        MMA16816(d[mt][np * 2 + 0], afr[mt][s], b0, b2);
                        MMA16816(d[mt][np * 2 + 1], afr[mt][s], b1, b3);
                    }
                }
            }
        }
        __syncthreads();
        if (t + 1 < NT) GSTORE(t + 1, (t + 1) & 1);
    }
    __syncthreads();

    float* sc = (float*)sm;
#pragma unroll
    for (int mt = 0; mt < 2; mt++) {
#pragma unroll
        for (int np = 0; np < 3; np++)
#pragma unroll
            for (int hh = 0; hh < 2; hh++) {
                int row0 = mwarp * 32 + mt * 16 + (lane >> 2);
                int col0 = nwarp * 48 + np * 16 + hh * 8 + 2 * (lane & 3);
                const float* dd = d[mt][np * 2 + hh];
                if (col0 < NC) sc[row0 * 97 + col0] = g_bias[col0] - dd[0];
                if (col0 + 1 < NC) sc[row0 * 97 + col0 + 1] = g_bias[col0 + 1] - dd[1];
                if (col0 < NC) sc[(row0 + 8) * 97 + col0] = g_bias[col0] - dd[2];
                if (col0 + 1 < NC) sc[(row0 + 8) * 97 + col0 + 1] = g_bias[col0 + 1] - dd[3];
            }
    }
    __syncthreads();

    if (tid < BMG) {
        int gi = i0 + tid;
        const float* row = sc + tid * 97;
        float best = 3e38f;
        int bc = 0;
#pragma unroll 4
        for (int cc = 0; cc < NC; cc++) {
            float v = row[cc];
            if (v < best) { best = v; bc = cc; }
        }
        out[gi] = (float)bc;
        // candidate bitmask: classes within THR of best
        unsigned mk0 = 0, mk1 = 0, mk2 = 0;
        int ncand = 0;
        float lim = best + THR;
#pragma unroll 4
        for (int cc = 0; cc < NC; cc++) {
            if (row[cc] < lim) {
                ncand++;
                if (cc < 32) mk0 |= 1u << cc;
                else if (cc < 64) mk1 |= 1u << (cc - 32);
                else mk2 |= 1u << (cc - 64);
            }
        }
        if (ncand > 1) {
            int slot = atomicAdd(&g_nfix, 1);
            if (slot < NI) {
                g_fix[slot] = gi;
                g_fixm[slot * 3 + 0] = mk0;
                g_fixm[slot * 3 + 1] = mk1;
                g_fixm[slot * 3 + 2] = mk2;
            }
        }
        unsigned bal = __ballot_sync(0xffffffffu, bc == labels[gi]);
        if ((tid & 31) == 0) atomicAdd(&g_count, __popc(bal));
    }
}

// ---------------------------------------------------------------------------
// Update path (blocks 0..80): CHUNKED sequential update, T=8 (R10 structure).
// ---------------------------------------------------------------------------
__device__ __forceinline__ void update_path(char* smu, const float* __restrict__ X,
                                            const int* __restrict__ labels,
                                            const float* __restrict__ mem,
                                            const int* __restrict__ mpos,
                                            float* __restrict__ out) {
    const int c = blockIdx.x, tid = threadIdx.x;
    const int w = tid >> 5, lane = tid & 31;

    float* s_part = (float*)(smu + 131072);
    float* s_red  = (float*)(smu + 192512);
    int*   s_list = (int*)(smu + 193024);
    int*   s_wcnt = (int*)(smu + 197120);
    int*   s_cnt  = (int*)(smu + 197152);

    const int SEG = NI / 8;
    const int base = w * SEG;
    const int4* lab4 = (const int4*)labels;
    int cnt = 0;
    for (int it = 0; it < SEG / 128; it++) {
        int4 v = lab4[(base >> 2) + it * 32 + lane];
        cnt += (v.x == c) + (v.y == c) + (v.z == c) + (v.w == c);
    }
#pragma unroll
    for (int o = 16; o; o >>= 1) cnt += __shfl_xor_sync(0xffffffffu, cnt, o);
    if (lane == 0) s_wcnt[w] = cnt;
    __syncthreads();
    if (tid == 0) {
        int t = 0;
        for (int ww = 0; ww < 8; ww++) { int v = s_wcnt[ww]; s_wcnt[ww] = t; t += v; }
        *s_cnt = t;
    }
    __syncthreads();
    int off = s_wcnt[w];
    for (int it = 0; it < SEG / 128; it++) {
        int gidx = base + it * 128 + lane * 4;
        int4 v = lab4[gidx >> 2];
        int m0 = (v.x == c), m1 = (v.y == c), m2 = (v.z == c), m3 = (v.w == c);
        int nm = m0 + m1 + m2 + m3;
        int x = nm;
#pragma unroll
        for (int o = 1; o < 32; o <<= 1) {
            int y = __shfl_up_sync(0xffffffffu, x, o);
            if (lane >= o) x += y;
        }
        int p2 = off + x - nm;
        if (m0) { s_list[p2 < 1024 ? p2 : 1023] = gidx + 0; p2++; }
        if (m1) { s_list[p2 < 1024 ? p2 : 1023] = gidx + 1; p2++; }
        if (m2) { s_list[p2 < 1024 ? p2 : 1023] = gidx + 2; p2++; }
        if (m3) { s_list[p2 < 1024 ? p2 : 1023] = gidx + 3; p2++; }
        off += __shfl_sync(0xffffffffu, x, 31);
    }
    __syncthreads();

    const int n = *s_cnt < 1024 ? *s_cnt : 1024;

    const uint32_t ring0 = smem_u32(smu) + tid * 16;
#pragma unroll
    for (int r = 0; r < 8; r++) {
        if (r < n) {
            const float* src = X + (size_t)s_list[r] * DIM + tid * 4;
            CPA16(ring0 + r * 8192, src);
            CPA16(ring0 + r * 8192 + 4096, src + 1024);
        }
    }
    CPCOMMIT();

    const ulonglong2* memU = (const ulonglong2*)mem + (size_t)c * BK * (DIM / 4);
    ulonglong2 br[BK][2];
#pragma unroll
    for (int j = 0; j < BK; j++) {
        br[j][0] = memU[j * 512 + tid];
        br[j][1] = memU[j * 512 + 256 + tid];
    }

#define REDROWS(CNT, ROFF)                                                    \
    for (int rid = w; rid < (CNT); rid += 8) {                                \
        const float4* rp = (const float4*)(s_part + rid * 256);               \
        float4 a0 = rp[lane], a1 = rp[lane + 32];                             \
        float v = (a0.x + a0.y) + (a0.z + a0.w) + (a1.x + a1.y) + (a1.z + a1.w); \
        _Pragma("unroll") for (int o = 16; o; o >>= 1)                        \
            v += __shfl_xor_sync(0xffffffffu, v, o);                          \
        if (lane == 0) s_red[(ROFF) + rid] = v;                               \
    }

#pragma unroll
    for (int j = 0; j < BK; j++)
        s_part[j * 256 + tid] = pdot(br[j][0], br[j][1], br[j][0], br[j][1]);
    __syncthreads();
    REDROWS(10, 0);
    __syncthreads();
    float bn[BK];
#pragma unroll
    for (int j = 0; j < BK; j++) bn[j] = s_red[j];

    int p = mpos[c];
    const int nch = (n + 7) >> 3;
    for (int ch = 0; ch < nch; ch++) {
        const int s0 = ch << 3;
        int cl = n - s0; if (cl > 8) cl = 8;
        const int buf = ch & 1;

        CPWAIT0();
        ulonglong2 xr[8][2];
        {
            const char* rb = smu + buf * 65536 + tid * 16;
#pragma unroll
            for (int r = 0; r < 8; r++) {
                xr[r][0] = *(const ulonglong2*)(rb + r * 8192);
                xr[r][1] = *(const ulonglong2*)(rb + r * 8192 + 4096);
            }
        }
        {
            const uint32_t rn = smem_u32(smu) + (buf ^ 1) * 65536 + tid * 16;
#pragma unroll
            for (int r = 0; r < 8; r++) {
                int g = s0 + 8 + r;
                if (g < n) {
                    const float* src = X + (size_t)s_list[g] * DIM + tid * 4;
                    CPA16(rn + r * 8192, src);
                    CPA16(rn + r * 8192 + 4096, src + 1024);
                }
            }
            CPCOMMIT();
        }

#pragma unroll
        for (int t = 0; t < 6; t++)
#pragma unroll
            for (int j = 0; j < BK; j++)
                s_part[(t * 10 + j) * 256 + tid] =
                    pdot(br[j][0], br[j][1], xr[t][0], xr[t][1]);
        __syncthreads();
        REDROWS(60, 0);
        __syncthreads();

#pragma unroll
        for (int t = 6; t < 8; t++)
#pragma unroll
            for (int j = 0; j < BK; j++)
                s_part[((t - 6) * 10 + j) * 256 + tid] =
                    pdot(br[j][0], br[j][1], xr[t][0], xr[t][1]);
        {
            int k = 20;
#pragma unroll
            for (int t = 1; t < 8; t++)
#pragma unroll
                for (int i = 0; i < t; i++) {
                    s_part[k * 256 + tid] =
                        pdot(xr[i][0], xr[i][1], xr[t][0], xr[t][1]);
                    k++;
                }
        }
#pragma unroll
        for (int t = 0; t < 8; t++)
            s_part[(48 + t) * 256 + tid] =
                pdot(xr[t][0], xr[t][1], xr[t][0], xr[t][1]);
        __syncthreads();
        REDROWS(56, 60);
        __syncthreads();

        int own[BK];
#pragma unroll
        for (int j = 0; j < BK; j++) own[j] = -1;
        for (int t = 0; t < cl; t++) {
            const int tri = 80 + ((t * (t - 1)) >> 1);
            const float xx = s_red[108 + t];
            int slot;
            if (p < BK) {
                slot = p; p++;
            } else {
                float dd[BK];
#pragma unroll
                for (int j = 0; j < BK; j++) {
                    int oj = own[j];
                    int idx = (oj < 0) ? (t * 10 + j) : (tri + oj);
                    dd[j] = fmaf(-2.f, s_red[idx], bn[j]);
                }
                float mx = dd[0];
#pragma unroll
                for (int j = 1; j < BK; j++) mx = fmaxf(mx, dd[j]);
                slot = BK - 1;
#pragma unroll
                for (int j = BK - 1; j >= 0; j--) slot = (dd[j] == mx) ? j : slot;
            }
#pragma unroll
            for (int j = 0; j < BK; j++) {
                bn[j]  = (slot == j) ? xx : bn[j];
                own[j] = (slot == j) ? t  : own[j];
            }
        }

        {
            const char* rb = smu + buf * 65536 + tid * 16;
#pragma unroll
            for (int j = 0; j < BK; j++) {
                int oj = own[j];
                if (oj >= 0) {
                    br[j][0] = *(const ulonglong2*)(rb + oj * 8192);
                    br[j][1] = *(const ulonglong2*)(rb + oj * 8192 + 4096);
                }
            }
        }
    }

    float* om = out + (NI + 1) + (size_t)c * BK * DIM;
#pragma unroll
    for (int j = 0; j < BK; j++) {
        float f0, f1, f2, f3;
        UNPACK2(f0, f1, br[j][0].x); UNPACK2(f2, f3, br[j][0].y);
        int d0 = j * DIM + tid * 4;
        om[d0 + 0] = f0; om[d0 + 1] = f1; om[d0 + 2] = f2; om[d0 + 3] = f3;
        UNPACK2(f0, f1, br[j][1].x); UNPACK2(f2, f3, br[j][1].y);
        int d1 = j * DIM + 1024 + tid * 4;
        om[d1 + 0] = f0; om[d1 + 1] = f1; om[d1 + 2] = f2; om[d1 + 3] = f3;
    }
    if (tid == 0) out[(NI + 1) + (size_t)NC * BK * DIM + c] = (float)p;
}

// ---------------------------------------------------------------------------
__global__ void __launch_bounds__(256, 1)
k_fused(const float* __restrict__ X, const int* __restrict__ labels,
        const float* __restrict__ mem, const int* __restrict__ mpos,
        float* __restrict__ out) {
    extern __shared__ char smdyn[];
    if (blockIdx.x < NC)
        update_path(smdyn, X, labels, mem, mpos, out);
    else
        gemm_path(smdyn, X, labels, out, blockIdx.x - NC);
}

// ---------------------------------------------------------------------------
// Fixup: exact fp32 re-check of the CANDIDATE classes only (bitmask-guided).
// Last block finalizes accuracy.
// ---------------------------------------------------------------------------
__global__ void __launch_bounds__(256) k_fixup(const float* __restrict__ X,
                                               const int* __restrict__ labels,
                                               float* __restrict__ out) {
    const int tid = threadIdx.x, w = tid >> 5, lane = tid & 31;
    __shared__ int   s_cand[NC];
    __shared__ float s_sc[NC];
    __shared__ int   s_nc;
    const int nfix = g_nfix < NI ? g_nfix : NI;
    for (int idx = blockIdx.x; idx < nfix; idx += gridDim.x) {
        const int gi = g_fix[idx];
        if (tid == 0) {
            int k = 0;
            unsigned m0 = g_fixm[idx * 3], m1 = g_fixm[idx * 3 + 1], m2 = g_fixm[idx * 3 + 2];
            for (int cc = 0; cc < NC; cc++) {
                unsigned mw = (cc < 32) ? m0 : (cc < 64) ? m1 : m2;
                if ((mw >> (cc & 31)) & 1u) s_cand[k++] = cc;
            }
            s_nc = k;
        }
        __syncthreads();
        const int ncd = s_nc;
        const float4* x4 = (const float4*)(X + (size_t)gi * DIM);
        for (int ci = w; ci < ncd; ci += 8) {
            int c = s_cand[ci];
            const float4* m4 = (const float4*)(g_mmean + (size_t)c * DIM);
            float s = 0.f;
#pragma unroll
            for (int k = 0; k < 16; k++) {
                float4 a = x4[k * 32 + lane];
                float4 b = m4[k * 32 + lane];
                s += a.x * b.x + a.y * b.y + a.z * b.z + a.w * b.w;
            }
#pragma unroll
            for (int o = 16; o; o >>= 1) s += __shfl_xor_sync(0xffffffffu, s, o);
            if (lane == 0) s_sc[ci] = g_bias[c] - s;
        }
        __syncthreads();
        if (tid == 0) {
            float best = 3e38f;
            int bc = 0;
            for (int ci = 0; ci < ncd; ci++) {
                float v = s_sc[ci];
                if (v < best) { best = v; bc = s_cand[ci]; }
            }
            int oldbc = (int)out[gi];
            if (oldbc != bc) {
                int lab = labels[gi];
                atomicAdd(&g_count, (bc == lab) - (oldbc == lab));
                out[gi] = (float)bc;
            }
        }
        __syncthreads();
    }
    __syncthreads();
    if (tid == 0) {
        __threadfence();
        int tk = atomicAdd(&g_tick, 1);
        if (tk == (int)gridDim.x - 1)
            out[NI] = (float)atomicAdd(&g_count, 0) * (1.0f / NI);
    }
}

// ---------------------------------------------------------------------------
extern "C" void kernel_launch(void* const* d_in, const int* in_sizes, int n_in,
                              void* d_out, int out_size) {
    const float* X      = (const float*)d_in[0];
    const int*   labels = (const int*)d_in[1];
    const float* mem    = (const float*)d_in[2];
    const int*   mpos   = (const int*)d_in[3];
    float* out = (float*)d_out;

    static bool init = false;
    if (!init) {
        init = true;
        cudaFuncSetAttribute(k_fused, cudaFuncAttributeMaxDynamicSharedMemorySize, SMEM_FUSED);
    }

    k_mean<<<NCP, 256>>>(mem);
    k_fused<<<NC + NI / BMG, 256, SMEM_FUSED>>>(X, labels, mem, mpos, out);
    k_fixup<<<296, 256>>>(X, labels, out);
}